// round 2
// baseline (speedup 1.0000x reference)
#include <cuda_runtime.h>
#include <cstdint>

// Problem constants
constexpr int Bn = 8192;   // batch
constexpr int Dn = 1024;   // input dim
constexpr int Hn = 400;    // hidden
constexpr int Ln = 256;    // half output
constexpr int En = 16;     // experts
constexpr int K2 = 512;    // 2L

#define TILE_M 64
#define MAX_TILES 160      // >= B/TILE_M + E = 144

// ---- device scratch (no allocations allowed) ----
__device__ int   g_counts[En];
__device__ int   g_offsets[En + 1];
__device__ int   g_cursor[En];
__device__ int   g_is64;
__device__ int   g_angle[Bn];
__device__ int   g_idx_sorted[Bn];
__device__ int   g_tile_expert[MAX_TILES];
__device__ int   g_tile_rowstart[MAX_TILES];
__device__ int   g_tile_rows[MAX_TILES];
__device__ float g_h1[(size_t)Bn * Hn];   // 13.1 MB intermediate, sorted row order

// ---- small prep kernels ----
__global__ void reset_kernel() {
    int t = threadIdx.x;
    if (t < En) { g_counts[t] = 0; g_cursor[t] = 0; }
    if (t == 0) g_is64 = 1;
}

// angle_idx may be int64 (reference dtype) or int32 (JAX x64 disabled).
// Interpret as int64 over the first B/2 entries (always within the smaller
// buffer); if any value is out of [0, E) the data must be int32.
__global__ void detect_kernel(const long long* __restrict__ ai) {
    int t = blockIdx.x * blockDim.x + threadIdx.x;
    if (t < Bn / 2) {
        long long v = ai[t];
        if (v < 0 || v >= En) g_is64 = 0;
    }
}

__global__ void convert_count_kernel(const void* __restrict__ ai) {
    int t = blockIdx.x * blockDim.x + threadIdx.x;
    if (t < Bn) {
        int v = g_is64 ? (int)((const long long*)ai)[t]
                       : ((const int*)ai)[t];
        g_angle[t] = v;
        atomicAdd(&g_counts[v], 1);
    }
}

__global__ void prefix_kernel() {
    if (threadIdx.x == 0) {
        int off = 0;
        for (int e = 0; e < En; e++) { g_offsets[e] = off; off += g_counts[e]; }
        g_offsets[En] = off;
        int t = 0;
        for (int e = 0; e < En; e++) {
            for (int r = 0; r < g_counts[e]; r += TILE_M) {
                g_tile_expert[t]   = e;
                g_tile_rowstart[t] = g_offsets[e] + r;
                int rem = g_counts[e] - r;
                g_tile_rows[t]     = rem < TILE_M ? rem : TILE_M;
                t++;
            }
        }
        for (; t < MAX_TILES; t++) g_tile_rows[t] = 0;
    }
}

__global__ void scatter_kernel() {
    int t = blockIdx.x * blockDim.x + threadIdx.x;
    if (t < Bn) {
        int e = g_angle[t];
        int pos = atomicAdd(&g_cursor[e], 1);
        g_idx_sorted[g_offsets[e] + pos] = t;
    }
}

// ---- GEMM1: h1 = relu(Xg @ W1[e] + b1[e]),  Xg gathered rows, K=1024, N=400 ----
// Block tile 64x128, BK=16, 256 threads, thread tile 8x4.
__global__ __launch_bounds__(256) void gemm1_kernel(const float* __restrict__ x,
                                                    const float* __restrict__ W1,
                                                    const float* __restrict__ b1) {
    int bt   = blockIdx.x;
    int rows = g_tile_rows[bt];
    if (rows == 0) return;
    int e       = g_tile_expert[bt];
    int rs      = g_tile_rowstart[bt];
    int colbase = blockIdx.y * 128;

    __shared__ float  Xs[16][66];     // stride 66 -> conflict-free transposed store
    __shared__ float4 Ws[16][32];

    int tid   = threadIdx.x;
    int row_l = tid >> 2;             // 0..63 (X-load row)
    int kk_l  = (tid & 3) << 2;       // 0,4,8,12
    int rl    = row_l < rows ? row_l : 0;
    const float* xrow = x + (size_t)g_idx_sorted[rs + rl] * Dn;

    int ty = tid >> 5;                // 0..7 row group
    int tx = tid & 31;                // 0..31 col group

    float acc[8][4];
#pragma unroll
    for (int i = 0; i < 8; i++)
#pragma unroll
        for (int j = 0; j < 4; j++) acc[i][j] = 0.f;

    const float* W1e = W1 + (size_t)e * Dn * Hn;

    for (int k0 = 0; k0 < Dn; k0 += 16) {
        float4 xv = *reinterpret_cast<const float4*>(xrow + k0 + kk_l);
        Xs[kk_l + 0][row_l] = xv.x;
        Xs[kk_l + 1][row_l] = xv.y;
        Xs[kk_l + 2][row_l] = xv.z;
        Xs[kk_l + 3][row_l] = xv.w;
#pragma unroll
        for (int i = 0; i < 2; i++) {
            int f4   = tid + 256 * i;       // 0..511
            int krow = f4 >> 5;             // 0..15
            int c4   = f4 & 31;
            int col  = colbase + c4 * 4;
            float4 wv = make_float4(0.f, 0.f, 0.f, 0.f);
            if (col < Hn)
                wv = *reinterpret_cast<const float4*>(W1e + (size_t)(k0 + krow) * Hn + col);
            Ws[krow][c4] = wv;
        }
        __syncthreads();
#pragma unroll
        for (int kk = 0; kk < 16; kk++) {
            float xr[8];
#pragma unroll
            for (int i = 0; i < 8; i++) xr[i] = Xs[kk][ty * 8 + i];
            float4 wv = Ws[kk][tx];
#pragma unroll
            for (int i = 0; i < 8; i++) {
                acc[i][0] += xr[i] * wv.x;
                acc[i][1] += xr[i] * wv.y;
                acc[i][2] += xr[i] * wv.z;
                acc[i][3] += xr[i] * wv.w;
            }
        }
        __syncthreads();
    }

    int col = colbase + tx * 4;
    if (col < Hn) {
        float4 bias = *reinterpret_cast<const float4*>(b1 + e * Hn + col);
#pragma unroll
        for (int i = 0; i < 8; i++) {
            int r = ty * 8 + i;
            if (r < rows) {
                float4 v;
                v.x = fmaxf(acc[i][0] + bias.x, 0.f);
                v.y = fmaxf(acc[i][1] + bias.y, 0.f);
                v.z = fmaxf(acc[i][2] + bias.z, 0.f);
                v.w = fmaxf(acc[i][3] + bias.w, 0.f);
                *reinterpret_cast<float4*>(g_h1 + (size_t)(rs + r) * Hn + col) = v;
            }
        }
    }
}

// ---- GEMM2: out = h1 @ W2[e] + b2[e], scatter rows; K=400, N=512 ----
__global__ __launch_bounds__(256) void gemm2_kernel(const float* __restrict__ W2,
                                                    const float* __restrict__ b2,
                                                    float* __restrict__ out) {
    int bt   = blockIdx.x;
    int rows = g_tile_rows[bt];
    if (rows == 0) return;
    int e       = g_tile_expert[bt];
    int rs      = g_tile_rowstart[bt];
    int colbase = blockIdx.y * 128;

    __shared__ float  Xs[16][66];
    __shared__ float4 Ws[16][32];

    int tid   = threadIdx.x;
    int row_l = tid >> 2;
    int kk_l  = (tid & 3) << 2;
    int rl    = row_l < rows ? row_l : rows - 1;
    const float* xrow = g_h1 + (size_t)(rs + rl) * Hn;

    int ty = tid >> 5;
    int tx = tid & 31;

    float acc[8][4];
#pragma unroll
    for (int i = 0; i < 8; i++)
#pragma unroll
        for (int j = 0; j < 4; j++) acc[i][j] = 0.f;

    const float* W2e = W2 + (size_t)e * Hn * K2;

    for (int k0 = 0; k0 < Hn; k0 += 16) {   // 25 iterations
        float4 xv = *reinterpret_cast<const float4*>(xrow + k0 + kk_l);
        Xs[kk_l + 0][row_l] = xv.x;
        Xs[kk_l + 1][row_l] = xv.y;
        Xs[kk_l + 2][row_l] = xv.z;
        Xs[kk_l + 3][row_l] = xv.w;
#pragma unroll
        for (int i = 0; i < 2; i++) {
            int f4   = tid + 256 * i;
            int krow = f4 >> 5;
            int c4   = f4 & 31;
            int col  = colbase + c4 * 4;
            Ws[krow][c4] = *reinterpret_cast<const float4*>(W2e + (size_t)(k0 + krow) * K2 + col);
        }
        __syncthreads();
#pragma unroll
        for (int kk = 0; kk < 16; kk++) {
            float xr[8];
#pragma unroll
            for (int i = 0; i < 8; i++) xr[i] = Xs[kk][ty * 8 + i];
            float4 wv = Ws[kk][tx];
#pragma unroll
            for (int i = 0; i < 8; i++) {
                acc[i][0] += xr[i] * wv.x;
                acc[i][1] += xr[i] * wv.y;
                acc[i][2] += xr[i] * wv.z;
                acc[i][3] += xr[i] * wv.w;
            }
        }
        __syncthreads();
    }

    int col = colbase + tx * 4;
    float4 bias = *reinterpret_cast<const float4*>(b2 + e * K2 + col);
#pragma unroll
    for (int i = 0; i < 8; i++) {
        int r = ty * 8 + i;
        if (r < rows) {
            int b = g_idx_sorted[rs + r];
            float4 v;
            v.x = acc[i][0] + bias.x;
            v.y = acc[i][1] + bias.y;
            v.z = acc[i][2] + bias.z;
            v.w = acc[i][3] + bias.w;
            // output layout: [z_mu (B,L) ; z_logvar (B,L)]
            float* dst = (col < Ln)
                ? out + (size_t)b * Ln + col
                : out + (size_t)Bn * Ln + (size_t)b * Ln + (col - Ln);
            *reinterpret_cast<float4*>(dst) = v;
        }
    }
}

extern "C" void kernel_launch(void* const* d_in, const int* in_sizes, int n_in,
                              void* d_out, int out_size) {
    const float* x  = (const float*)d_in[0];
    const void*  ai = d_in[1];
    const float* W1 = (const float*)d_in[2];
    const float* b1 = (const float*)d_in[3];
    const float* W2 = (const float*)d_in[4];
    const float* b2 = (const float*)d_in[5];
    float* out = (float*)d_out;

    reset_kernel<<<1, 32>>>();
    detect_kernel<<<(Bn / 2 + 255) / 256, 256>>>((const long long*)ai);
    convert_count_kernel<<<(Bn + 255) / 256, 256>>>(ai);
    prefix_kernel<<<1, 1>>>();
    scatter_kernel<<<(Bn + 255) / 256, 256>>>();

    dim3 grid(MAX_TILES, 4);
    gemm1_kernel<<<grid, 256>>>(x, W1, b1);
    gemm2_kernel<<<grid, 256>>>(W2, b2, out);
}

// round 4
// speedup vs baseline: 1.9083x; 1.9083x over previous
#include <cuda_runtime.h>
#include <cuda_bf16.h>
#include <cstdint>

// Problem constants
constexpr int Bn = 8192;   // batch
constexpr int Dn = 1024;   // input dim (K1)
constexpr int Hn = 400;    // hidden
constexpr int Ln = 256;    // half output
constexpr int En = 16;     // experts
constexpr int K2n = 512;   // 2L (N of GEMM2)
constexpr int HP = 448;    // hidden padded to 64 (K of GEMM2)
constexpr int NW = 512;    // padded N rows for transposed weights

#define TILE_M 128
#define MAX_TILES 96       // >= B/128 + E = 80

// ================= device scratch (zero-init, no allocs) =================
__device__ int   g_counts[En];
__device__ int   g_offsets[En + 1];
__device__ int   g_cursor[En];
__device__ int   g_is64;
__device__ int   g_angle[Bn];
__device__ int   g_idx_sorted[Bn + TILE_M];
__device__ int   g_tile_expert[MAX_TILES];
__device__ int   g_tile_rowstart[MAX_TILES];
__device__ int   g_tile_rows[MAX_TILES];

// bf16 hi/lo buffers, uint4 for 16B alignment
__device__ uint4 g_x_hi[(size_t)Bn * Dn / 8];              // [Bn][1024] bf16
__device__ uint4 g_x_lo[(size_t)Bn * Dn / 8];
__device__ uint4 g_w1t_hi[(size_t)En * NW * Dn / 8];       // [E][512][1024] (n,k)
__device__ uint4 g_w1t_lo[(size_t)En * NW * Dn / 8];
__device__ uint4 g_w2t_hi[(size_t)En * NW * HP / 8];       // [E][512][448] (n,k)
__device__ uint4 g_w2t_lo[(size_t)En * NW * HP / 8];
__device__ uint4 g_h1_hi[(size_t)(Bn + TILE_M) * HP / 8];  // [rows][448]
__device__ uint4 g_h1_lo[(size_t)(Bn + TILE_M) * HP / 8];

// ================= helpers =================
__device__ __forceinline__ uint32_t smem_u32(const void* p) {
    uint32_t a;
    asm("{ .reg .u64 t; cvta.to.shared.u64 t, %1; cvt.u32.u64 %0, t; }" : "=r"(a) : "l"(p));
    return a;
}

#define CP16(dst_u32, src_ptr) \
    asm volatile("cp.async.cg.shared.global [%0], [%1], 16;" :: "r"(dst_u32), "l"(src_ptr))
#define CP_COMMIT() asm volatile("cp.async.commit_group;" ::: "memory")
#define CP_WAIT1()  asm volatile("cp.async.wait_group 1;" ::: "memory")
#define CP_WAIT0()  asm volatile("cp.async.wait_group 0;" ::: "memory")

__device__ __forceinline__ void mma16816(float* d, const uint32_t* a, const uint32_t* b) {
    asm volatile(
        "mma.sync.aligned.m16n8k16.row.col.f32.bf16.bf16.f32 "
        "{%0,%1,%2,%3}, {%4,%5,%6,%7}, {%8,%9}, {%0,%1,%2,%3};"
        : "+f"(d[0]), "+f"(d[1]), "+f"(d[2]), "+f"(d[3])
        : "r"(a[0]), "r"(a[1]), "r"(a[2]), "r"(a[3]), "r"(b[0]), "r"(b[1]));
}

__device__ __forceinline__ void split2(float v0, float v1, uint32_t& hi, uint32_t& lo) {
    __nv_bfloat16 h0 = __float2bfloat16(v0);
    __nv_bfloat16 h1 = __float2bfloat16(v1);
    __nv_bfloat16 l0 = __float2bfloat16(v0 - __bfloat162float(h0));
    __nv_bfloat16 l1 = __float2bfloat16(v1 - __bfloat162float(h1));
    __nv_bfloat162 ph; ph.x = h0; ph.y = h1;
    __nv_bfloat162 pl; pl.x = l0; pl.y = l1;
    hi = *reinterpret_cast<uint32_t*>(&ph);
    lo = *reinterpret_cast<uint32_t*>(&pl);
}

// ================= prep kernels =================
__global__ void reset_kernel() {
    int t = threadIdx.x;
    if (t < En) { g_counts[t] = 0; g_cursor[t] = 0; }
    if (t == 0) g_is64 = 1;
    if (t < TILE_M) g_idx_sorted[Bn + t] = 0;
}

__global__ void detect_kernel(const long long* __restrict__ ai) {
    int t = blockIdx.x * blockDim.x + threadIdx.x;
    if (t < Bn / 2) {
        long long v = ai[t];
        if (v < 0 || v >= En) g_is64 = 0;
    }
}

__global__ void convert_count_kernel(const void* __restrict__ ai) {
    int t = blockIdx.x * blockDim.x + threadIdx.x;
    if (t < Bn) {
        int v = g_is64 ? (int)((const long long*)ai)[t] : ((const int*)ai)[t];
        g_angle[t] = v;
        atomicAdd(&g_counts[v], 1);
    }
}

__global__ void prefix_kernel() {
    if (threadIdx.x == 0) {
        int off = 0;
        for (int e = 0; e < En; e++) { g_offsets[e] = off; off += g_counts[e]; }
        g_offsets[En] = off;
        int t = 0;
        for (int e = 0; e < En; e++) {
            for (int r = 0; r < g_counts[e]; r += TILE_M) {
                g_tile_expert[t]   = e;
                g_tile_rowstart[t] = g_offsets[e] + r;
                int rem = g_counts[e] - r;
                g_tile_rows[t]     = rem < TILE_M ? rem : TILE_M;
                t++;
            }
        }
        for (; t < MAX_TILES; t++) g_tile_rows[t] = 0;
    }
}

__global__ void scatter_kernel() {
    int t = blockIdx.x * blockDim.x + threadIdx.x;
    if (t < Bn) {
        int e = g_angle[t];
        int pos = atomicAdd(&g_cursor[e], 1);
        g_idx_sorted[g_offsets[e] + pos] = t;
    }
}

// ================= conversions =================
__global__ void split_x_kernel(const float* __restrict__ x) {
    int i = blockIdx.x * blockDim.x + threadIdx.x;
    if (i < Bn * Dn / 4) {
        float4 v = reinterpret_cast<const float4*>(x)[i];
        uint32_t h0, l0, h1, l1;
        split2(v.x, v.y, h0, l0);
        split2(v.z, v.w, h1, l1);
        uint32_t* xh = reinterpret_cast<uint32_t*>(g_x_hi);
        uint32_t* xl = reinterpret_cast<uint32_t*>(g_x_lo);
        xh[i * 2] = h0; xh[i * 2 + 1] = h1;
        xl[i * 2] = l0; xl[i * 2 + 1] = l1;
    }
}

// W1 [E][1024(k)][400(n)] -> [E][512(n)][1024(k)] hi/lo, n>=400 zero
__global__ void tw1_kernel(const float* __restrict__ W1) {
    __shared__ float t[32][33];
    int e = blockIdx.z, k0 = blockIdx.x * 32, n0 = blockIdx.y * 32;
    int tx = threadIdx.x, ty = threadIdx.y;   // 32 x 8
    const float* W = W1 + (size_t)e * Dn * Hn;
#pragma unroll
    for (int i = 0; i < 32; i += 8) {
        int k = k0 + ty + i, n = n0 + tx;
        t[ty + i][tx] = (n < Hn) ? W[(size_t)k * Hn + n] : 0.f;
    }
    __syncthreads();
    __nv_bfloat16* wh = reinterpret_cast<__nv_bfloat16*>(g_w1t_hi);
    __nv_bfloat16* wl = reinterpret_cast<__nv_bfloat16*>(g_w1t_lo);
#pragma unroll
    for (int i = 0; i < 32; i += 8) {
        int n = n0 + ty + i, k = k0 + tx;
        float v = t[tx][ty + i];
        __nv_bfloat16 h = __float2bfloat16(v);
        size_t o = ((size_t)e * NW + n) * Dn + k;
        wh[o] = h;
        wl[o] = __float2bfloat16(v - __bfloat162float(h));
    }
}

// W2 [E][400(k)][512(n)] -> [E][512(n)][448(k)] hi/lo, k>=400 zero
__global__ void tw2_kernel(const float* __restrict__ W2) {
    __shared__ float t[32][33];
    int e = blockIdx.z, k0 = blockIdx.x * 32, n0 = blockIdx.y * 32;
    int tx = threadIdx.x, ty = threadIdx.y;
    const float* W = W2 + (size_t)e * Hn * K2n;
#pragma unroll
    for (int i = 0; i < 32; i += 8) {
        int k = k0 + ty + i, n = n0 + tx;
        t[ty + i][tx] = (k < Hn) ? W[(size_t)k * K2n + n] : 0.f;
    }
    __syncthreads();
    __nv_bfloat16* wh = reinterpret_cast<__nv_bfloat16*>(g_w2t_hi);
    __nv_bfloat16* wl = reinterpret_cast<__nv_bfloat16*>(g_w2t_lo);
#pragma unroll
    for (int i = 0; i < 32; i += 8) {
        int n = n0 + ty + i, k = k0 + tx;
        float v = t[tx][ty + i];
        __nv_bfloat16 h = __float2bfloat16(v);
        size_t o = ((size_t)e * NW + n) * HP + k;
        wh[o] = h;
        wl[o] = __float2bfloat16(v - __bfloat162float(h));
    }
}

// ================= mma.sync GEMM kernels =================
// smem: [0,512) idx, [512,1024) bias, [1024..) two 40KB stages
// stage layout: Ahi @0, Alo @10240, Bhi @20480, Blo @30720  (row stride 80B)
#define STAGE_SZ 40960
#define SMEM_SZ  (1024 + 2 * STAGE_SZ)

struct Frags {
    float acc[2][8][4];
    uint32_t ah[2][4], al[2][4], bb[8][2];
};

// compute one BK=32 chunk from stage buffer
__device__ __forceinline__ void compute_chunk(const char* st, int wm, int wn,
                                              int tq, int tr, Frags& F) {
#pragma unroll
    for (int ks = 0; ks < 2; ks++) {
        const char* As = st;             // A hi
        const char* Bs = st + 20480;     // B hi
        int kb = ks * 32 + tr * 4;       // byte offset of k within row
#pragma unroll
        for (int mt = 0; mt < 2; mt++) {
            int r0 = wm * 32 + mt * 16 + tq;
            F.ah[mt][0] = *(const uint32_t*)(As + r0 * 80 + kb);
            F.ah[mt][1] = *(const uint32_t*)(As + (r0 + 8) * 80 + kb);
            F.ah[mt][2] = *(const uint32_t*)(As + r0 * 80 + kb + 16);
            F.ah[mt][3] = *(const uint32_t*)(As + (r0 + 8) * 80 + kb + 16);
            F.al[mt][0] = *(const uint32_t*)(As + 10240 + r0 * 80 + kb);
            F.al[mt][1] = *(const uint32_t*)(As + 10240 + (r0 + 8) * 80 + kb);
            F.al[mt][2] = *(const uint32_t*)(As + 10240 + r0 * 80 + kb + 16);
            F.al[mt][3] = *(const uint32_t*)(As + 10240 + (r0 + 8) * 80 + kb + 16);
        }
#pragma unroll
        for (int nt = 0; nt < 8; nt++) {
            int n = wn * 64 + nt * 8 + tq;
            F.bb[nt][0] = *(const uint32_t*)(Bs + n * 80 + kb);
            F.bb[nt][1] = *(const uint32_t*)(Bs + n * 80 + kb + 16);
        }
#pragma unroll
        for (int mt = 0; mt < 2; mt++)
#pragma unroll
            for (int nt = 0; nt < 8; nt++) {
                mma16816(F.acc[mt][nt], F.ah[mt], F.bb[nt]);   // hh
                mma16816(F.acc[mt][nt], F.al[mt], F.bb[nt]);   // lh
            }
#pragma unroll
        for (int nt = 0; nt < 8; nt++) {
            int n = wn * 64 + nt * 8 + tq;
            F.bb[nt][0] = *(const uint32_t*)(Bs + 10240 + n * 80 + kb);
            F.bb[nt][1] = *(const uint32_t*)(Bs + 10240 + n * 80 + kb + 16);
        }
#pragma unroll
        for (int mt = 0; mt < 2; mt++)
#pragma unroll
            for (int nt = 0; nt < 8; nt++)
                mma16816(F.acc[mt][nt], F.ah[mt], F.bb[nt]);   // hl
    }
}

// GEMM1: relu(Xg @ W1t^T + b1) -> h1 hi/lo.  K=1024, 32 iters.
__global__ __launch_bounds__(256) void gemm1_mma(const float* __restrict__ b1) {
    int bt = blockIdx.x;
    int rows = g_tile_rows[bt];
    if (rows == 0) return;
    int e  = g_tile_expert[bt];
    int rs = g_tile_rowstart[bt];
    int colbase = blockIdx.y * 128;

    extern __shared__ char smem[];
    uint32_t sb = smem_u32(smem);
    int tid = threadIdx.x;
    int wid = tid >> 5, lane = tid & 31;
    int wm = wid & 3, wn = wid >> 2;
    int tq = lane >> 2, tr = lane & 3;

    int* idx_s = reinterpret_cast<int*>(smem);
    float* bias_s = reinterpret_cast<float*>(smem + 512);
    if (tid < TILE_M) idx_s[tid] = g_idx_sorted[rs + tid];
    if (tid < 128) {
        int col = colbase + tid;
        bias_s[tid] = (col < Hn) ? b1[e * Hn + col] : 0.f;
    }
    __syncthreads();

    const uint4* w1h = g_w1t_hi + (size_t)e * NW * (Dn / 8);
    const uint4* w1l = g_w1t_lo + (size_t)e * NW * (Dn / 8);

    // pipeline fill helper (BK=32 -> 4 uint4 per row)
    auto fill = [&](int stg, int kt) {
        uint32_t base = sb + 1024 + stg * STAGE_SZ;
#pragma unroll
        for (int i = tid; i < 512; i += 256) {
            int r = i >> 2, c4 = i & 3;
            uint32_t dA = base + r * 80 + c4 * 16;
            size_t ao = (size_t)idx_s[r] * 128 + kt * 4 + c4;
            CP16(dA,         g_x_hi + ao);
            CP16(dA + 10240, g_x_lo + ao);
            uint32_t dB = base + 20480 + r * 80 + c4 * 16;
            size_t bo = (size_t)(colbase + r) * 128 + kt * 4 + c4;
            CP16(dB,         w1h + bo);
            CP16(dB + 10240, w1l + bo);
        }
    };

    Frags F;
#pragma unroll
    for (int mt = 0; mt < 2; mt++)
#pragma unroll
        for (int nt = 0; nt < 8; nt++)
#pragma unroll
            for (int j = 0; j < 4; j++) F.acc[mt][nt][j] = 0.f;

    fill(0, 0); CP_COMMIT();
    for (int it = 0; it < 32; it++) {
        if (it + 1 < 32) { fill((it + 1) & 1, it + 1); CP_COMMIT(); CP_WAIT1(); }
        else CP_WAIT0();
        __syncthreads();
        compute_chunk(smem + 1024 + (it & 1) * STAGE_SZ, wm, wn, tq, tr, F);
        __syncthreads();
    }

    // epilogue: bias + relu + bf16 split -> h1
    uint32_t* h1h = reinterpret_cast<uint32_t*>(g_h1_hi);
    uint32_t* h1l = reinterpret_cast<uint32_t*>(g_h1_lo);
#pragma unroll
    for (int mt = 0; mt < 2; mt++) {
        int r0 = wm * 32 + mt * 16 + tq;
#pragma unroll
        for (int nt = 0; nt < 8; nt++) {
            int c = wn * 64 + nt * 8 + tr * 2;    // local col (even)
            int gcol = colbase + c;
            if (gcol >= HP) continue;
#pragma unroll
            for (int half = 0; half < 2; half++) {
                int r = r0 + half * 8;
                if (r >= rows) continue;
                float a0 = F.acc[mt][nt][half * 2];
                float a1 = F.acc[mt][nt][half * 2 + 1];
                float v0 = (gcol < Hn)     ? fmaxf(a0 + bias_s[c], 0.f)     : 0.f;
                float v1 = (gcol + 1 < Hn) ? fmaxf(a1 + bias_s[c + 1], 0.f) : 0.f;
                uint32_t hi, lo;
                split2(v0, v1, hi, lo);
                size_t o = ((size_t)(rs + r) * HP + gcol) >> 1;
                h1h[o] = hi;
                h1l[o] = lo;
            }
        }
    }
}

// GEMM2: h1 @ W2t^T + b2 -> scattered out.  K=448, 14 iters.
__global__ __launch_bounds__(256) void gemm2_mma(const float* __restrict__ b2,
                                                 float* __restrict__ out) {
    int bt = blockIdx.x;
    int rows = g_tile_rows[bt];
    if (rows == 0) return;
    int e  = g_tile_expert[bt];
    int rs = g_tile_rowstart[bt];
    int colbase = blockIdx.y * 128;

    extern __shared__ char smem[];
    uint32_t sb = smem_u32(smem);
    int tid = threadIdx.x;
    int wid = tid >> 5, lane = tid & 31;
    int wm = wid & 3, wn = wid >> 2;
    int tq = lane >> 2, tr = lane & 3;

    int* idx_s = reinterpret_cast<int*>(smem);
    float* bias_s = reinterpret_cast<float*>(smem + 512);
    if (tid < TILE_M) idx_s[tid] = g_idx_sorted[rs + tid];
    if (tid < 128) bias_s[tid] = b2[e * K2n + colbase + tid];
    __syncthreads();

    const uint4* w2h = g_w2t_hi + (size_t)e * NW * (HP / 8);
    const uint4* w2l = g_w2t_lo + (size_t)e * NW * (HP / 8);

    auto fill = [&](int stg, int kt) {
        uint32_t base = sb + 1024 + stg * STAGE_SZ;
#pragma unroll
        for (int i = tid; i < 512; i += 256) {
            int r = i >> 2, c4 = i & 3;
            uint32_t dA = base + r * 80 + c4 * 16;
            size_t ao = (size_t)(rs + r) * (HP / 8) + kt * 4 + c4;
            CP16(dA,         g_h1_hi + ao);
            CP16(dA + 10240, g_h1_lo + ao);
            uint32_t dB = base + 20480 + r * 80 + c4 * 16;
            size_t bo = (size_t)(colbase + r) * (HP / 8) + kt * 4 + c4;
            CP16(dB,         w2h + bo);
            CP16(dB + 10240, w2l + bo);
        }
    };

    Frags F;
#pragma unroll
    for (int mt = 0; mt < 2; mt++)
#pragma unroll
        for (int nt = 0; nt < 8; nt++)
#pragma unroll
            for (int j = 0; j < 4; j++) F.acc[mt][nt][j] = 0.f;

    fill(0, 0); CP_COMMIT();
    for (int it = 0; it < 14; it++) {
        if (it + 1 < 14) { fill((it + 1) & 1, it + 1); CP_COMMIT(); CP_WAIT1(); }
        else CP_WAIT0();
        __syncthreads();
        compute_chunk(smem + 1024 + (it & 1) * STAGE_SZ, wm, wn, tq, tr, F);
        __syncthreads();
    }

    // epilogue: bias + scatter to (z_mu ; z_logvar)
#pragma unroll
    for (int mt = 0; mt < 2; mt++) {
        int r0 = wm * 32 + mt * 16 + tq;
#pragma unroll
        for (int nt = 0; nt < 8; nt++) {
            int c = wn * 64 + nt * 8 + tr * 2;
            int gcol = colbase + c;
#pragma unroll
            for (int half = 0; half < 2; half++) {
                int r = r0 + half * 8;
                if (r >= rows) continue;
                int b = idx_s[r];
                float2 v;
                v.x = F.acc[mt][nt][half * 2]     + bias_s[c];
                v.y = F.acc[mt][nt][half * 2 + 1] + bias_s[c + 1];
                float* dst = (gcol < Ln)
                    ? out + (size_t)b * Ln + gcol
                    : out + (size_t)Bn * Ln + (size_t)b * Ln + (gcol - Ln);
                *reinterpret_cast<float2*>(dst) = v;
            }
        }
    }
}

// ================= launch =================
extern "C" void kernel_launch(void* const* d_in, const int* in_sizes, int n_in,
                              void* d_out, int out_size) {
    const float* x  = (const float*)d_in[0];
    const void*  ai = d_in[1];
    const float* W1 = (const float*)d_in[2];
    const float* b1 = (const float*)d_in[3];
    const float* W2 = (const float*)d_in[4];
    const float* b2 = (const float*)d_in[5];
    float* out = (float*)d_out;

    cudaFuncSetAttribute(gemm1_mma, cudaFuncAttributeMaxDynamicSharedMemorySize, SMEM_SZ);
    cudaFuncSetAttribute(gemm2_mma, cudaFuncAttributeMaxDynamicSharedMemorySize, SMEM_SZ);

    reset_kernel<<<1, 128>>>();
    detect_kernel<<<(Bn / 2 + 255) / 256, 256>>>((const long long*)ai);
    convert_count_kernel<<<(Bn + 255) / 256, 256>>>(ai);
    prefix_kernel<<<1, 1>>>();
    scatter_kernel<<<(Bn + 255) / 256, 256>>>();

    split_x_kernel<<<(Bn * Dn / 4 + 255) / 256, 256>>>(x);
    tw1_kernel<<<dim3(Dn / 32, NW / 32, En), dim3(32, 8)>>>(W1);
    tw2_kernel<<<dim3(HP / 32, NW / 32, En), dim3(32, 8)>>>(W2);

    gemm1_mma<<<dim3(MAX_TILES, 4), 256, SMEM_SZ>>>(b1);
    gemm2_mma<<<dim3(MAX_TILES, 4), 256, SMEM_SZ>>>(b2, out);
}